// round 5
// baseline (speedup 1.0000x reference)
#include <cuda_runtime.h>

typedef unsigned long long u64;

__device__ __forceinline__ u64 pack2(float x, float y) {
    u64 r; asm("mov.b64 %0, {%1, %2};" : "=l"(r) : "f"(x), "f"(y)); return r;
}
__device__ __forceinline__ u64 pack2dup(float x) {
    u64 r; asm("mov.b64 %0, {%1, %1};" : "=l"(r) : "f"(x)); return r;
}
__device__ __forceinline__ void unpack2(u64 v, float& x, float& y) {
    asm("mov.b64 {%0, %1}, %2;" : "=f"(x), "=f"(y) : "l"(v));
}
__device__ __forceinline__ u64 ffma2(u64 a, u64 b, u64 c) {
    u64 d; asm("fma.rn.f32x2 %0, %1, %2, %3;" : "=l"(d) : "l"(a), "l"(b), "l"(c));
    return d;
}

#define HS 34   // feature row stride: float2 word idx = 17*lane + k/2 -> conflict-free
#define AS 66   // adjacency row stride

// constant image layout (floats)
#define OFF_W1(l) ((l) * 1024)
#define OFF_B1(l) (3072 + (l) * 32)
#define OFF_W2(l) (3168 + (l) * 1024)
#define OFF_B2(l) (6240 + (l) * 32)
#define OFF_SCW1  6336
#define OFF_SCB1  6592
#define OFF_SCW2  6608
#define OFF_SCB2  6624
#define CC_FLOATS 6640

__constant__ float CC[CC_FLOATS];
__device__   float g_stage[CC_FLOATS];

__global__ void pack_kernel(
    const float* __restrict__ w1_0, const float* __restrict__ b1_0,
    const float* __restrict__ w2_0, const float* __restrict__ b2_0,
    const float* __restrict__ w1_1, const float* __restrict__ b1_1,
    const float* __restrict__ w2_1, const float* __restrict__ b2_1,
    const float* __restrict__ w1_2, const float* __restrict__ b1_2,
    const float* __restrict__ w2_2, const float* __restrict__ b2_2,
    const float* __restrict__ sc_w1, const float* __restrict__ sc_b1,
    const float* __restrict__ sc_w2, const float* __restrict__ sc_b2)
{
    const int i = blockIdx.x * blockDim.x + threadIdx.x;
    if (i < 512)  g_stage[OFF_W1(0) + i] = w1_0[i];
    if (i < 1024) {
        g_stage[OFF_W1(1) + i] = w1_1[i];
        g_stage[OFF_W1(2) + i] = w1_2[i];
        g_stage[OFF_W2(0) + i] = w2_0[i];
        g_stage[OFF_W2(1) + i] = w2_1[i];
        g_stage[OFF_W2(2) + i] = w2_2[i];
    }
    if (i < 32) {
        g_stage[OFF_B1(0) + i] = b1_0[i];
        g_stage[OFF_B1(1) + i] = b1_1[i];
        g_stage[OFF_B1(2) + i] = b1_2[i];
        g_stage[OFF_B2(0) + i] = b2_0[i];
        g_stage[OFF_B2(1) + i] = b2_1[i];
        g_stage[OFF_B2(2) + i] = b2_2[i];
    }
    if (i < 256) g_stage[OFF_SCW1 + i] = sc_w1[i];
    if (i < 16)  { g_stage[OFF_SCB1 + i] = sc_b1[i]; g_stage[OFF_SCW2 + i] = sc_w2[i]; }
    if (i == 0)  g_stage[OFF_SCB2] = sc_b2[0];
}

// Z[n][o] = H[n][o] + sum_k A[n][k]*H[k][o]; W = 16 or 32 channels
template<int W>
__device__ __forceinline__ void agg_f(const float* __restrict__ H,
                                      float* __restrict__ Z,
                                      const float* __restrict__ Af, int t)
{
    constexpr int OG = W / 8;          // 2 or 4
    if (t < 32 * OG) {
        const int o0 = (t & (OG - 1)) * 8;
        const int n0 = (t / (OG)) * 2, n1 = n0 + 1;
        u64 a0[4], a1[4];
        #pragma unroll
        for (int j = 0; j < 4; j++) {
            const float2 s0 = *(const float2*)(H + n0 * HS + o0 + 2 * j);
            const float2 s1 = *(const float2*)(H + n1 * HS + o0 + 2 * j);
            a0[j] = pack2(s0.x, s0.y);
            a1[j] = pack2(s1.x, s1.y);
        }
        #pragma unroll 2
        for (int k = 0; k < 64; k += 2) {
            u64 h0[4], h1[4];
            #pragma unroll
            for (int j = 0; j < 4; j++) {
                const float2 v0 = *(const float2*)(H + k * HS + o0 + 2 * j);
                const float2 v1 = *(const float2*)(H + (k + 1) * HS + o0 + 2 * j);
                h0[j] = pack2(v0.x, v0.y);
                h1[j] = pack2(v1.x, v1.y);
            }
            const float2 cA = *(const float2*)(Af + n0 * AS + k);
            const float2 cB = *(const float2*)(Af + n1 * AS + k);
            const u64 cA0 = pack2dup(cA.x), cA1 = pack2dup(cA.y);
            const u64 cB0 = pack2dup(cB.x), cB1 = pack2dup(cB.y);
            #pragma unroll
            for (int j = 0; j < 4; j++) {
                a0[j] = ffma2(cA0, h0[j], a0[j]);
                a1[j] = ffma2(cB0, h0[j], a1[j]);
                a0[j] = ffma2(cA1, h1[j], a0[j]);
                a1[j] = ffma2(cB1, h1[j], a1[j]);
            }
        }
        #pragma unroll
        for (int j = 0; j < 4; j++) {
            float x, y;
            unpack2(a0[j], x, y);
            *(float2*)(Z + n0 * HS + o0 + 2 * j) = make_float2(x, y);
            unpack2(a1[j], x, y);
            *(float2*)(Z + n1 * HS + o0 + 2 * j) = make_float2(x, y);
        }
    }
}

// zout[n][o] = relu(b[o] + sum_k z[n][k]*W[k][o]); weights/bias from CC.
// 4 warps; warp owns 8 outputs o0 = 8*warp (uniform LDC); lane owns nodes lane, lane+32.
template<int DIN>
__device__ __forceinline__ void gemm_c(const float* __restrict__ zin,
                                       float* __restrict__ zout,
                                       const int woff, const int boff, int t)
{
    const int lane = t & 31;
    const int o0 = (t >> 5) * 8;
    u64 a0[4], a1[4];
    {
        const float4 b0 = *(const float4*)&CC[boff + o0];
        const float4 b1 = *(const float4*)&CC[boff + o0 + 4];
        a0[0] = pack2(b0.x, b0.y); a0[1] = pack2(b0.z, b0.w);
        a0[2] = pack2(b1.x, b1.y); a0[3] = pack2(b1.z, b1.w);
        a1[0] = a0[0]; a1[1] = a0[1]; a1[2] = a0[2]; a1[3] = a0[3];
    }
    const float* z0 = zin + lane * HS;
    const float* z1 = zin + (lane + 32) * HS;
    #pragma unroll
    for (int k = 0; k < DIN; k += 2) {
        const float2 v0 = *(const float2*)(z0 + k);
        const float2 v1 = *(const float2*)(z1 + k);
        const float4 wa0 = *(const float4*)&CC[woff + k * 32 + o0];
        const float4 wa1 = *(const float4*)&CC[woff + k * 32 + o0 + 4];
        const float4 wb0 = *(const float4*)&CC[woff + (k + 1) * 32 + o0];
        const float4 wb1 = *(const float4*)&CC[woff + (k + 1) * 32 + o0 + 4];
        const u64 pa0 = pack2(wa0.x, wa0.y), pa1 = pack2(wa0.z, wa0.w);
        const u64 pa2 = pack2(wa1.x, wa1.y), pa3 = pack2(wa1.z, wa1.w);
        const u64 pb0 = pack2(wb0.x, wb0.y), pb1 = pack2(wb0.z, wb0.w);
        const u64 pb2 = pack2(wb1.x, wb1.y), pb3 = pack2(wb1.z, wb1.w);
        const u64 v0x = pack2dup(v0.x), v0y = pack2dup(v0.y);
        const u64 v1x = pack2dup(v1.x), v1y = pack2dup(v1.y);
        a0[0] = ffma2(v0x, pa0, a0[0]); a0[1] = ffma2(v0x, pa1, a0[1]);
        a0[2] = ffma2(v0x, pa2, a0[2]); a0[3] = ffma2(v0x, pa3, a0[3]);
        a1[0] = ffma2(v1x, pa0, a1[0]); a1[1] = ffma2(v1x, pa1, a1[1]);
        a1[2] = ffma2(v1x, pa2, a1[2]); a1[3] = ffma2(v1x, pa3, a1[3]);
        a0[0] = ffma2(v0y, pb0, a0[0]); a0[1] = ffma2(v0y, pb1, a0[1]);
        a0[2] = ffma2(v0y, pb2, a0[2]); a0[3] = ffma2(v0y, pb3, a0[3]);
        a1[0] = ffma2(v1y, pb0, a1[0]); a1[1] = ffma2(v1y, pb1, a1[1]);
        a1[2] = ffma2(v1y, pb2, a1[2]); a1[3] = ffma2(v1y, pb3, a1[3]);
    }
    #pragma unroll
    for (int j = 0; j < 4; j++) {
        float x, y;
        unpack2(a0[j], x, y);
        *(float2*)(zout + lane * HS + o0 + 2 * j) =
            make_float2(fmaxf(x, 0.f), fmaxf(y, 0.f));
        unpack2(a1[j], x, y);
        *(float2*)(zout + (lane + 32) * HS + o0 + 2 * j) =
            make_float2(fmaxf(x, 0.f), fmaxf(y, 0.f));
    }
}

__global__ void __launch_bounds__(128, 6)
seal_kernel(
    const int* __restrict__ labels,
    const int* __restrict__ src,
    const int* __restrict__ dst,
    const float* __restrict__ emb,
    const float* __restrict__ conv1_w, const float* __restrict__ conv1_b,
    const float* __restrict__ conv2_w, const float* __restrict__ conv2_b,
    float* __restrict__ out)
{
    // pool union:
    //  GIN phase : A[64*66=4224] | bufA[64*34=2176]@4224 | bufB@6400 (..8576)
    //  conv1     : weights stride-165 (5280) + bias @5280 (overwrites A/bufA; cur=bufB)
    //  conv2     : weights stride-165 (2640) + bias @2640
    __shared__ __align__(16) float pool[8576];
    __shared__ float pooled[10 * 33];
    __shared__ float ybuf[32 * 5];
    __shared__ float c2buf[16 * 5];
    __shared__ float feat[16];
    __shared__ float hidbuf[16];
    __shared__ int   nodeOfRank[10];

    float* A    = pool;
    float* bufA = pool + 4224;
    float* bufB = pool + 6400;

    const int g = blockIdx.x;
    const int t = threadIdx.x;

    // ---- dense adjacency: A[dst][src] += 1 ----
    {
        const float4 z4 = make_float4(0.f, 0.f, 0.f, 0.f);
        for (int idx = t; idx < 4224 / 4; idx += 128)
            *(float4*)(A + idx * 4) = z4;
    }
    __syncthreads();
    #pragma unroll
    for (int half = 0; half < 2; half++) {
        const int4 s4 = ((const int4*)(src + (g << 10)))[t + half * 128];
        const int4 d4 = ((const int4*)(dst + (g << 10)))[t + half * 128];
        atomicAdd(&A[(d4.x & 63) * AS + (s4.x & 63)], 1.0f);
        atomicAdd(&A[(d4.y & 63) * AS + (s4.y & 63)], 1.0f);
        atomicAdd(&A[(d4.z & 63) * AS + (s4.z & 63)], 1.0f);
        atomicAdd(&A[(d4.w & 63) * AS + (s4.w & 63)], 1.0f);
    }

    // ---- DRNL embedding -> bufA (64 x 16, stride HS) ----
    {
        const int n = t >> 1, c0 = (t & 1) * 8;
        const float4 v0 = *(const float4*)(emb + labels[(g << 6) + n] * 16 + c0);
        const float4 v1 = *(const float4*)(emb + labels[(g << 6) + n] * 16 + c0 + 4);
        *(float2*)(bufA + n * HS + c0)     = make_float2(v0.x, v0.y);
        *(float2*)(bufA + n * HS + c0 + 2) = make_float2(v0.z, v0.w);
        *(float2*)(bufA + n * HS + c0 + 4) = make_float2(v1.x, v1.y);
        *(float2*)(bufA + n * HS + c0 + 6) = make_float2(v1.z, v1.w);
    }
    __syncthreads();

    // ---- 3 GIN layers ----
    float* cur = bufA;
    float* oth = bufB;

    // layer 0 (din=16)
    agg_f<16>(cur, oth, A, t);  __syncthreads();
    gemm_c<16>(oth, cur, OFF_W1(0), OFF_B1(0), t);  __syncthreads();
    gemm_c<32>(cur, oth, OFF_W2(0), OFF_B2(0), t);  __syncthreads();
    cur = bufB; oth = bufA;
    // layer 1
    agg_f<32>(cur, oth, A, t);  __syncthreads();
    gemm_c<32>(oth, cur, OFF_W1(1), OFF_B1(1), t);  __syncthreads();
    gemm_c<32>(cur, oth, OFF_W2(1), OFF_B2(1), t);  __syncthreads();
    cur = bufA; oth = bufB;
    // layer 2
    agg_f<32>(cur, oth, A, t);  __syncthreads();
    gemm_c<32>(oth, cur, OFF_W1(2), OFF_B1(2), t);  __syncthreads();
    gemm_c<32>(cur, oth, OFF_W2(2), OFF_B2(2), t);  __syncthreads();
    cur = bufB;   // final features live in bufB (6400..8575) — safe from conv staging

    // ---- SortPooling: stable rank by channel 31 desc, keep 10 ----
    if (t < 64) {
        const float key = cur[t * HS + 31];
        int r = 0;
        for (int m = 0; m < 64; m++) {
            const float km = cur[m * HS + 31];
            r += (km > key) || (km == key && m < t);
        }
        if (r < 10) nodeOfRank[r] = t;
    }
    __syncthreads();

    // pooled copy + conv1 weight staging (independent regions)
    for (int idx = t; idx < 10 * 32; idx += 128) {
        const int k = idx >> 5, c = idx & 31;
        pooled[k * 33 + c] = cur[nodeOfRank[k] * HS + c];
    }
    for (int idx = t; idx < 32 * 160; idx += 128) {
        const int co = idx / 160, r = idx - co * 160;
        pool[co * 165 + r] = conv1_w[idx];
    }
    if (t < 32) pool[5280 + t] = conv1_b[t];
    __syncthreads();

    // ---- Conv1 (32->32,k=5,pad=2) + ReLU + MaxPool(2,2) ----
    for (int idx = t; idx < 160; idx += 128) {
        const int co = idx & 31, q = idx >> 5;
        float a0 = pool[5280 + co];
        float a1 = a0;
        const float* wrow = pool + co * 165;
        for (int ci = 0; ci < 32; ci++) {
            #pragma unroll
            for (int k = 0; k < 5; k++) {
                const float w = wrow[ci * 5 + k];
                const int p0 = 2 * q + k - 2;
                const int p1 = p0 + 1;
                if (p0 >= 0 && p0 < 10) a0 += w * pooled[p0 * 33 + ci];
                if (p1 >= 0 && p1 < 10) a1 += w * pooled[p1 * 33 + ci];
            }
        }
        ybuf[co * 5 + q] = fmaxf(fmaxf(a0, 0.f), fmaxf(a1, 0.f));
    }
    __syncthreads();

    // ---- Conv2 (32->16,k=5,pad=2) + ReLU ----
    for (int idx = t; idx < 16 * 160; idx += 128) {
        const int co = idx / 160, r = idx - co * 160;
        pool[co * 165 + r] = conv2_w[idx];
    }
    if (t < 16) pool[2640 + t] = conv2_b[t];
    __syncthreads();

    if (t < 80) {
        const int co = t & 15, p = t >> 4;
        float a = pool[2640 + co];
        const float* wrow = pool + co * 165;
        for (int ci = 0; ci < 32; ci++) {
            #pragma unroll
            for (int k = 0; k < 5; k++) {
                const int q = p + k - 2;
                if (q >= 0 && q < 5) a += wrow[ci * 5 + k] * ybuf[ci * 5 + q];
            }
        }
        c2buf[co * 5 + p] = fmaxf(a, 0.f);
    }
    __syncthreads();

    // ---- mean + scorer MLP (weights from CC) ----
    if (t < 16) {
        feat[t] = 0.2f * (c2buf[t * 5 + 0] + c2buf[t * 5 + 1] + c2buf[t * 5 + 2] +
                          c2buf[t * 5 + 3] + c2buf[t * 5 + 4]);
    }
    __syncthreads();
    if (t < 16) {
        float a = CC[OFF_SCB1 + t];
        #pragma unroll
        for (int i = 0; i < 16; i++) a += feat[i] * CC[OFF_SCW1 + i * 16 + t];
        hidbuf[t] = fmaxf(a, 0.f);
    }
    __syncthreads();
    if (t == 0) {
        float s = CC[OFF_SCB2];
        #pragma unroll
        for (int j = 0; j < 16; j++) s += hidbuf[j] * CC[OFF_SCW2 + j];
        out[g] = s;
    }
}

extern "C" void kernel_launch(void* const* d_in, const int* in_sizes, int n_in,
                              void* d_out, int out_size)
{
    const int B = in_sizes[0] / 64;

    pack_kernel<<<4, 256>>>(
        (const float*)d_in[4],  (const float*)d_in[5],
        (const float*)d_in[6],  (const float*)d_in[7],
        (const float*)d_in[8],  (const float*)d_in[9],
        (const float*)d_in[10], (const float*)d_in[11],
        (const float*)d_in[12], (const float*)d_in[13],
        (const float*)d_in[14], (const float*)d_in[15],
        (const float*)d_in[20], (const float*)d_in[21],
        (const float*)d_in[22], (const float*)d_in[23]);

    void* gs = nullptr;
    cudaGetSymbolAddress(&gs, g_stage);
    cudaMemcpyToSymbolAsync(CC, gs, CC_FLOATS * sizeof(float), 0,
                            cudaMemcpyDeviceToDevice, 0);

    seal_kernel<<<B, 128>>>(
        (const int*)d_in[0], (const int*)d_in[1], (const int*)d_in[2],
        (const float*)d_in[3],
        (const float*)d_in[16], (const float*)d_in[17],
        (const float*)d_in[18], (const float*)d_in[19],
        (float*)d_out);
}

// round 6
// speedup vs baseline: 1.8161x; 1.8161x over previous
#include <cuda_runtime.h>

typedef unsigned long long u64;

__device__ __forceinline__ u64 pack2(float x, float y) {
    u64 r; asm("mov.b64 %0, {%1, %2};" : "=l"(r) : "f"(x), "f"(y)); return r;
}
__device__ __forceinline__ u64 pack2dup(float x) {
    u64 r; asm("mov.b64 %0, {%1, %1};" : "=l"(r) : "f"(x)); return r;
}
__device__ __forceinline__ void unpack2(u64 v, float& x, float& y) {
    asm("mov.b64 {%0, %1}, %2;" : "=f"(x), "=f"(y) : "l"(v));
}
__device__ __forceinline__ u64 ffma2(u64 a, u64 b, u64 c) {
    u64 d; asm("fma.rn.f32x2 %0, %1, %2, %3;" : "=l"(d) : "l"(a), "l"(b), "l"(c));
    return d;
}

#define HS 36   // H row stride (mult of 4 -> float4 broadcast reads)
#define NS 64   // Zt row stride

// pool layout (floats):
//  GIN:  At[0..4096) | H0[4096..6400) | H1[6400..8704) | WB[8704..10816)
//        WB: w1@0, b1@1024, w2@1056, b2@2080
//  conv: raw1[co*165+r]@0 (5280) | c1b@5280 | pooledT@5312(384) | ybufT@5696(256)
//        c2buf@5952(80) | feat@6032(16) | hid@6048(16) ; raw2@0(2640)+c2b@2640
//        partials@8704 (4*320)
#define P_H0 4096
#define P_H1 6400
#define P_WB 8704
#define P_C1B 5280
#define P_PT  5312
#define P_YB  5696
#define P_C2  5952
#define P_FE  6032
#define P_HI  6048
#define P_C2B 2640
#define P_PART 8704

// ---- agg: Zt[c][n] = sum_k At[k][n? ] ... Z[n][c] = sum_k Abar[n][k]*H[k][c]
// lane = node (warp covers 32 nodes), warp also picks a channel half.
template<int W>
__device__ __forceinline__ void agg_t(const float* __restrict__ At,
                                      const float* __restrict__ H,
                                      float* __restrict__ Zt, int t)
{
    const int warp = t >> 5, lane = t & 31;
    const int nh = warp >> 1, oh = warp & 1;
    const int n = nh * 32 + lane;
    const int ob = oh * (W / 2);
    constexpr int NG = W / 8;    // float4 groups per half
    u64 acc[W / 4];
    #pragma unroll
    for (int j = 0; j < W / 4; j++) acc[j] = 0ull;

    #pragma unroll 2
    for (int k = 0; k < 64; k++) {
        const u64 ad = pack2dup(At[k * 64 + n]);     // per-lane scalar, 1 wf
        #pragma unroll
        for (int j = 0; j < NG; j++) {
            const float4 h = *(const float4*)&H[k * HS + ob + 4 * j];  // bcast
            acc[2 * j]     = ffma2(ad, pack2(h.x, h.y), acc[2 * j]);
            acc[2 * j + 1] = ffma2(ad, pack2(h.z, h.w), acc[2 * j + 1]);
        }
    }
    #pragma unroll
    for (int j = 0; j < W / 4; j++) {
        float x, y; unpack2(acc[j], x, y);
        Zt[(ob + 2 * j) * NS + n]     = x;
        Zt[(ob + 2 * j + 1) * NS + n] = y;
    }
}

// ---- gemm1: T1[n][o] = relu(b1[o] + sum_k Zt[k][n]*W1[k][o])
// lane = o; warp owns 16 nodes; acts broadcast float4 (4 nodes each).
template<int DIN>
__device__ __forceinline__ void gemm1_t(const float* __restrict__ Zt,
                                        float* __restrict__ T1,
                                        const float* __restrict__ WB, int t)
{
    const int lane = t & 31;
    const int nq = (t >> 5) * 16;
    u64 acc[8];
    {
        const u64 b = pack2dup(WB[1024 + lane]);
        #pragma unroll
        for (int j = 0; j < 8; j++) acc[j] = b;
    }
    #pragma unroll 2
    for (int k = 0; k < DIN; k++) {
        const u64 wd = pack2dup(WB[k * 32 + lane]);   // per-lane scalar, 1 wf
        const float4 z0 = *(const float4*)&Zt[k * NS + nq];       // bcast
        const float4 z1 = *(const float4*)&Zt[k * NS + nq + 4];
        const float4 z2 = *(const float4*)&Zt[k * NS + nq + 8];
        const float4 z3 = *(const float4*)&Zt[k * NS + nq + 12];
        acc[0] = ffma2(wd, pack2(z0.x, z0.y), acc[0]);
        acc[1] = ffma2(wd, pack2(z0.z, z0.w), acc[1]);
        acc[2] = ffma2(wd, pack2(z1.x, z1.y), acc[2]);
        acc[3] = ffma2(wd, pack2(z1.z, z1.w), acc[3]);
        acc[4] = ffma2(wd, pack2(z2.x, z2.y), acc[4]);
        acc[5] = ffma2(wd, pack2(z2.z, z2.w), acc[5]);
        acc[6] = ffma2(wd, pack2(z3.x, z3.y), acc[6]);
        acc[7] = ffma2(wd, pack2(z3.z, z3.w), acc[7]);
    }
    #pragma unroll
    for (int j = 0; j < 8; j++) {
        float x, y; unpack2(acc[j], x, y);
        T1[(nq + 2 * j) * HS + lane]     = fmaxf(x, 0.f);
        T1[(nq + 2 * j + 1) * HS + lane] = fmaxf(y, 0.f);
    }
}

// ---- gemm2: H'[n][o] = relu(b2[o] + sum_k T1[n][k]*W2[k][o])
// lane = o; warp owns 16 nodes; acts broadcast float4 over k.
__device__ __forceinline__ void gemm2_t(const float* __restrict__ T1,
                                        float* __restrict__ Hout,
                                        const float* __restrict__ WB, int t)
{
    const int lane = t & 31;
    const int nq = (t >> 5) * 16;
    float acc[16];
    {
        const float b = WB[2080 + lane];
        #pragma unroll
        for (int j = 0; j < 16; j++) acc[j] = b;
    }
    #pragma unroll
    for (int kc = 0; kc < 8; kc++) {
        const float w0 = WB[1056 + (4 * kc + 0) * 32 + lane];
        const float w1 = WB[1056 + (4 * kc + 1) * 32 + lane];
        const float w2 = WB[1056 + (4 * kc + 2) * 32 + lane];
        const float w3 = WB[1056 + (4 * kc + 3) * 32 + lane];
        #pragma unroll
        for (int ni = 0; ni < 16; ni++) {
            const float4 v = *(const float4*)&T1[(nq + ni) * HS + 4 * kc]; // bcast
            acc[ni] = fmaf(w0, v.x, acc[ni]);
            acc[ni] = fmaf(w1, v.y, acc[ni]);
            acc[ni] = fmaf(w2, v.z, acc[ni]);
            acc[ni] = fmaf(w3, v.w, acc[ni]);
        }
    }
    #pragma unroll
    for (int ni = 0; ni < 16; ni++)
        Hout[(nq + ni) * HS + lane] = fmaxf(acc[ni], 0.f);
}

__global__ void __launch_bounds__(128, 5)
seal_kernel(
    const int* __restrict__ labels,
    const int* __restrict__ src,
    const int* __restrict__ dst,
    const float* __restrict__ emb,
    const float* __restrict__ w1_0, const float* __restrict__ b1_0,
    const float* __restrict__ w2_0, const float* __restrict__ b2_0,
    const float* __restrict__ w1_1, const float* __restrict__ b1_1,
    const float* __restrict__ w2_1, const float* __restrict__ b2_1,
    const float* __restrict__ w1_2, const float* __restrict__ b1_2,
    const float* __restrict__ w2_2, const float* __restrict__ b2_2,
    const float* __restrict__ conv1_w, const float* __restrict__ conv1_b,
    const float* __restrict__ conv2_w, const float* __restrict__ conv2_b,
    const float* __restrict__ sc_w1, const float* __restrict__ sc_b1,
    const float* __restrict__ sc_w2, const float* __restrict__ sc_b2,
    float* __restrict__ out)
{
    __shared__ __align__(16) float pool[10816];
    __shared__ int nor[10];

    float* At = pool;
    float* WB = pool + P_WB;

    const int g = blockIdx.x;
    const int t = threadIdx.x;

    // ---- zero At (transposed adjacency: At[k=src][n=dst] = Abar[n][k]) ----
    {
        const float4 z4 = make_float4(0.f, 0.f, 0.f, 0.f);
        #pragma unroll
        for (int i = 0; i < 8; i++)
            *(float4*)(At + (t + i * 128) * 4) = z4;
    }
    __syncthreads();

    // ---- edges + diagonal via atomics; embedding load in same phase ----
    {
        const int4* s4p = (const int4*)(src + (g << 10));
        const int4* d4p = (const int4*)(dst + (g << 10));
        #pragma unroll
        for (int i = 0; i < 2; i++) {
            const int4 s = s4p[t + i * 128];
            const int4 d = d4p[t + i * 128];
            atomicAdd(&At[(s.x & 63) * 64 + (d.x & 63)], 1.0f);
            atomicAdd(&At[(s.y & 63) * 64 + (d.y & 63)], 1.0f);
            atomicAdd(&At[(s.z & 63) * 64 + (d.z & 63)], 1.0f);
            atomicAdd(&At[(s.w & 63) * 64 + (d.w & 63)], 1.0f);
        }
        if (t < 64) atomicAdd(&At[t * 65], 1.0f);   // self term (I + A)
    }
    {
        const int n = t >> 1, c0 = (t & 1) * 8;
        const float4 v0 = *(const float4*)(emb + labels[(g << 6) + n] * 16 + c0);
        const float4 v1 = *(const float4*)(emb + labels[(g << 6) + n] * 16 + c0 + 4);
        *(float4*)(pool + P_H0 + n * HS + c0)     = v0;
        *(float4*)(pool + P_H0 + n * HS + c0 + 4) = v1;
    }
    __syncthreads();

    const float* W1s[3] = { w1_0, w1_1, w1_2 };
    const float* B1s[3] = { b1_0, b1_1, b1_2 };
    const float* W2s[3] = { w2_0, w2_1, w2_2 };
    const float* B2s[3] = { b2_0, b2_1, b2_2 };

    float* cur = pool + P_H0;
    float* oth = pool + P_H1;

    #pragma unroll
    for (int l = 0; l < 3; l++) {
        const int din = l ? 32 : 16;

        // stage layer weights into WB
        for (int idx = t; idx < din * 8; idx += 128)
            *(float4*)(WB + idx * 4) = *(const float4*)(W1s[l] + idx * 4);
        for (int idx = t; idx < 256; idx += 128)
            *(float4*)(WB + 1056 + idx * 4) = *(const float4*)(W2s[l] + idx * 4);
        if (t < 32) { WB[1024 + t] = B1s[l][t]; WB[2080 + t] = B2s[l][t]; }
        __syncthreads();

        // agg: cur -> Zt (in oth)
        if (din == 16) agg_t<16>(At, cur, oth, t);
        else           agg_t<32>(At, cur, oth, t);
        __syncthreads();

        // gemm1: Zt -> cur (overwrite consumed H)
        if (din == 16) gemm1_t<16>(oth, cur, WB, t);
        else           gemm1_t<32>(oth, cur, WB, t);
        __syncthreads();

        // gemm2: cur -> oth
        gemm2_t(cur, oth, WB, t);
        __syncthreads();

        float* tmp = cur; cur = oth; oth = tmp;
    }
    // cur == pool + P_H1 (3 swaps from H0)

    // ---- SortPooling: stable rank by channel 31 desc, keep 10 ----
    if (t < 64) {
        const float key = cur[t * HS + 31];
        int r = 0;
        for (int m = 0; m < 64; m++) {
            const float km = cur[m * HS + 31];
            r += (km > key) || (km == key && m < t);
        }
        if (r < 10) nor[r] = t;
    }
    __syncthreads();

    // ---- pooledT extraction (transposed, zero-padded) + conv1 staging ----
    for (int idx = t; idx < 384; idx += 128) {
        const int ci = idx / 12, r = idx - ci * 12;
        pool[P_PT + ci * 12 + r] = (r < 10) ? cur[nor[r] * HS + ci] : 0.f;
    }
    for (int idx = t; idx < 5120; idx += 128) {
        const int co = idx / 160, r = idx - co * 160;
        pool[co * 165 + r] = conv1_w[idx];
    }
    if (t < 32) pool[P_C1B + t] = conv1_b[t];
    __syncthreads();

    // ---- Conv1: 4 warps x 8 input channels; lane = co; acc over all 10 p ----
    {
        const int warp = t >> 5, lane = t & 31;
        float acc[10];
        #pragma unroll
        for (int p = 0; p < 10; p++) acc[p] = 0.f;
        for (int ci = warp * 8; ci < warp * 8 + 8; ci++) {
            float w[5];
            #pragma unroll
            for (int k = 0; k < 5; k++) w[k] = pool[lane * 165 + ci * 5 + k];
            const float4 va = *(const float4*)&pool[P_PT + ci * 12];     // r0..3
            const float4 vb = *(const float4*)&pool[P_PT + ci * 12 + 4]; // r4..7
            const float4 vc = *(const float4*)&pool[P_PT + ci * 12 + 8]; // r8..11 (10,11=0)
            const float v[12] = { va.x, va.y, va.z, va.w, vb.x, vb.y, vb.z, vb.w,
                                  vc.x, vc.y, vc.z, vc.w };
            #pragma unroll
            for (int p = 0; p < 10; p++) {
                #pragma unroll
                for (int k = 0; k < 5; k++) {
                    const int idx = p + k - 2;
                    if (idx >= 0) acc[p] = fmaf(w[k], v[idx], acc[p]);
                }
            }
        }
        #pragma unroll
        for (int p = 0; p < 10; p++)
            pool[P_PART + warp * 320 + lane * 10 + p] = acc[p];
    }
    __syncthreads();

    // ---- combine conv1 partials + bias + relu + maxpool -> ybufT[co][q] ----
    for (int idx = t; idx < 256; idx += 128) {
        if (idx < 160) {
            const int co = idx & 31, q = idx >> 5;
            float v0 = pool[P_C1B + co], v1 = v0;
            #pragma unroll
            for (int w = 0; w < 4; w++) {
                v0 += pool[P_PART + w * 320 + co * 10 + 2 * q];
                v1 += pool[P_PART + w * 320 + co * 10 + 2 * q + 1];
            }
            pool[P_YB + co * 8 + q] = fmaxf(fmaxf(v0, 0.f), fmaxf(v1, 0.f));
        } else {
            const int j = idx - 160;               // zero-pad q = 5..7
            const int co = j / 3, qq = 5 + (j - co * 3);
            pool[P_YB + co * 8 + qq] = 0.f;
        }
    }
    __syncthreads();

    // ---- conv2 weight staging (overwrites conv1 region) ----
    for (int idx = t; idx < 2560; idx += 128) {
        const int co = idx / 160, r = idx - co * 160;
        pool[co * 165 + r] = conv2_w[idx];
    }
    if (t < 16) pool[P_C2B + t] = conv2_b[t];
    __syncthreads();

    // ---- Conv2: 1 warp, lane<16 = co; p = 0..4 ----
    if (t < 16) {
        float acc[5];
        #pragma unroll
        for (int p = 0; p < 5; p++) acc[p] = pool[P_C2B + t];
        for (int ci = 0; ci < 32; ci++) {
            float w[5];
            #pragma unroll
            for (int k = 0; k < 5; k++) w[k] = pool[t * 165 + ci * 5 + k];
            const float4 ya = *(const float4*)&pool[P_YB + ci * 8];   // q0..3
            const float y4 = pool[P_YB + ci * 8 + 4];
            const float a[9] = { 0.f, 0.f, ya.x, ya.y, ya.z, ya.w, y4, 0.f, 0.f };
            #pragma unroll
            for (int p = 0; p < 5; p++)
                #pragma unroll
                for (int k = 0; k < 5; k++)
                    acc[p] = fmaf(w[k], a[p + k], acc[p]);
        }
        #pragma unroll
        for (int p = 0; p < 5; p++)
            pool[P_C2 + t * 5 + p] = fmaxf(acc[p], 0.f);
    }
    __syncthreads();

    // ---- mean + scorer MLP (tiny; scorer weights straight from global) ----
    if (t < 16) {
        pool[P_FE + t] = 0.2f * (pool[P_C2 + t * 5 + 0] + pool[P_C2 + t * 5 + 1] +
                                 pool[P_C2 + t * 5 + 2] + pool[P_C2 + t * 5 + 3] +
                                 pool[P_C2 + t * 5 + 4]);
    }
    __syncthreads();
    if (t < 16) {
        float a = sc_b1[t];
        #pragma unroll
        for (int i = 0; i < 16; i++) a = fmaf(pool[P_FE + i], sc_w1[i * 16 + t], a);
        pool[P_HI + t] = fmaxf(a, 0.f);
    }
    __syncthreads();
    if (t == 0) {
        float s = sc_b2[0];
        #pragma unroll
        for (int j = 0; j < 16; j++) s = fmaf(pool[P_HI + j], sc_w2[j], s);
        out[g] = s;
    }
}

extern "C" void kernel_launch(void* const* d_in, const int* in_sizes, int n_in,
                              void* d_out, int out_size)
{
    const int B = in_sizes[0] / 64;
    seal_kernel<<<B, 128>>>(
        (const int*)d_in[0], (const int*)d_in[1], (const int*)d_in[2],
        (const float*)d_in[3],
        (const float*)d_in[4],  (const float*)d_in[5],
        (const float*)d_in[6],  (const float*)d_in[7],
        (const float*)d_in[8],  (const float*)d_in[9],
        (const float*)d_in[10], (const float*)d_in[11],
        (const float*)d_in[12], (const float*)d_in[13],
        (const float*)d_in[14], (const float*)d_in[15],
        (const float*)d_in[16], (const float*)d_in[17],
        (const float*)d_in[18], (const float*)d_in[19],
        (const float*)d_in[20], (const float*)d_in[21],
        (const float*)d_in[22], (const float*)d_in[23],
        (float*)d_out);
}

// round 7
// speedup vs baseline: 2.3427x; 1.2900x over previous
#include <cuda_runtime.h>

typedef unsigned long long u64;
typedef unsigned int u32;

__device__ __forceinline__ u64 pack2(float x, float y) {
    u64 r; asm("mov.b64 %0, {%1, %2};" : "=l"(r) : "f"(x), "f"(y)); return r;
}
__device__ __forceinline__ u64 pack2dup(float x) {
    u64 r; asm("mov.b64 %0, {%1, %1};" : "=l"(r) : "f"(x)); return r;
}
__device__ __forceinline__ void unpack2(u64 v, float& x, float& y) {
    asm("mov.b64 {%0, %1}, %2;" : "=f"(x), "=f"(y) : "l"(v));
}
__device__ __forceinline__ u64 ffma2(u64 a, u64 b, u64 c) {
    u64 d; asm("fma.rn.f32x2 %0, %1, %2, %3;" : "=l"(d) : "l"(a), "l"(b), "l"(c));
    return d;
}

#define HS 36   // H row stride: ni-stride 36 -> banks 4 apart -> conflict-free frags

// pool layout (floats):
//  GIN : At8u[0..1024) | H0[1024..3328) | H1[3328..5632) | WB[5632..7744)
//        WB: w1@+0, b1@+1024, w2@+1056, b2@+2080
//  conv: conv1 w@0 (5280) + b@5280 | pooledT@5632(384) | partials@6016(1280)
//        ybufT@7296(256) | c2buf@7552(80) | feat@7632 | hid@7648
//        conv2 w@0 (2640) + b@2640
#define P_H0   1024
#define P_H1   3328
#define P_WB   5632
#define P_C1B  5280
#define P_PT   5632
#define P_PART 6016
#define P_YB   7296
#define P_C2   7552
#define P_FE   7632
#define P_HI   7648
#define P_C2B  2640

// ---- agg: Z[n][c] = sum_k A[n][k]*H[k][c], A from byte-packed At8 (incl. diag)
// warp: nhalf=(w&1)*32, chalf=(w>>1)*(W/2); lane=(ni*4+ci): nodes nhalf+ni+8g,
// channels c0=chalf+ci*2*PP (PP pairs).
template<int W>
__device__ __forceinline__ void agg_frag(const u32* __restrict__ At8,
                                         const float* __restrict__ H,
                                         float* __restrict__ Z, int t)
{
    constexpr int PP = W / 16;          // f32x2 pairs per lane: 2 (W=32) or 1 (W=16)
    const int warp = t >> 5, lane = t & 31;
    const int ni = lane >> 2, ci = lane & 3;
    const int nhalf = (warp & 1) * 32;
    const int chalf = (warp >> 1) * (W / 2);
    const int c0 = chalf + ci * (2 * PP);

    u64 acc[4][PP];
    #pragma unroll
    for (int g = 0; g < 4; g++)
        #pragma unroll
        for (int p = 0; p < PP; p++) acc[g][p] = 0ull;

    #pragma unroll 2
    for (int kb = 0; kb < 16; kb++) {
        u32 a4[4];
        #pragma unroll
        for (int g = 0; g < 4; g++)
            a4[g] = At8[kb * 64 + nhalf + ni + 8 * g];   // 8 distinct, multicast
        #pragma unroll
        for (int j = 0; j < 4; j++) {
            const int k = 4 * kb + j;
            u64 h[PP];
            if (PP == 2) {
                const float4 hv = *(const float4*)&H[k * HS + c0];
                h[0] = pack2(hv.x, hv.y); h[1] = pack2(hv.z, hv.w);
            } else {
                const float2 hv = *(const float2*)&H[k * HS + c0];
                h[0] = pack2(hv.x, hv.y);
            }
            #pragma unroll
            for (int g = 0; g < 4; g++) {
                const float af = (float)((a4[g] >> (8 * j)) & 0xffu);
                const u64 ad = pack2dup(af);
                #pragma unroll
                for (int p = 0; p < PP; p++)
                    acc[g][p] = ffma2(ad, h[p], acc[g][p]);
            }
        }
    }
    #pragma unroll
    for (int g = 0; g < 4; g++) {
        const int n = nhalf + ni + 8 * g;
        if (PP == 2) {
            float x0, y0, x1, y1;
            unpack2(acc[g][0], x0, y0); unpack2(acc[g][1], x1, y1);
            *(float4*)&Z[n * HS + c0] = make_float4(x0, y0, x1, y1);
        } else {
            float x0, y0;
            unpack2(acc[g][0], x0, y0);
            *(float2*)&Z[n * HS + c0] = make_float2(x0, y0);
        }
    }
}

// ---- gemm: Out[n][o] = relu(B[o] + sum_k Zin[n][k]*W[k][o]); 64 n x 32 o.
// warp: nhalf=(w&1)*32, ohalf=(w>>1)*16; lane=(ni*4+oi): o0=ohalf+4*oi.
template<int DIN>
__device__ __forceinline__ void gemm_frag(const float* __restrict__ Zin,
                                          float* __restrict__ Out,
                                          const float* __restrict__ W,
                                          const float* __restrict__ B, int t)
{
    const int warp = t >> 5, lane = t & 31;
    const int ni = lane >> 2, oi = lane & 3;
    const int nhalf = (warp & 1) * 32;
    const int o0 = (warp >> 1) * 16 + 4 * oi;

    u64 acc[4][2];
    {
        const float4 b4 = *(const float4*)&B[o0];
        const u64 b01 = pack2(b4.x, b4.y), b23 = pack2(b4.z, b4.w);
        #pragma unroll
        for (int g = 0; g < 4; g++) { acc[g][0] = b01; acc[g][1] = b23; }
    }
    #pragma unroll
    for (int kb = 0; kb < DIN / 4; kb++) {
        float4 zf[4];
        #pragma unroll
        for (int g = 0; g < 4; g++)
            zf[g] = *(const float4*)&Zin[(nhalf + ni + 8 * g) * HS + 4 * kb];
        #pragma unroll
        for (int j = 0; j < 4; j++) {
            const int k = 4 * kb + j;
            const float4 wv = *(const float4*)&W[k * 32 + o0];
            const u64 w01 = pack2(wv.x, wv.y), w23 = pack2(wv.z, wv.w);
            #pragma unroll
            for (int g = 0; g < 4; g++) {
                const float a = (j == 0) ? zf[g].x : (j == 1) ? zf[g].y :
                                (j == 2) ? zf[g].z : zf[g].w;
                const u64 ad = pack2dup(a);
                acc[g][0] = ffma2(ad, w01, acc[g][0]);
                acc[g][1] = ffma2(ad, w23, acc[g][1]);
            }
        }
    }
    #pragma unroll
    for (int g = 0; g < 4; g++) {
        float x0, y0, x1, y1;
        unpack2(acc[g][0], x0, y0); unpack2(acc[g][1], x1, y1);
        *(float4*)&Out[(nhalf + ni + 8 * g) * HS + o0] =
            make_float4(fmaxf(x0, 0.f), fmaxf(y0, 0.f),
                        fmaxf(x1, 0.f), fmaxf(y1, 0.f));
    }
}

__global__ void __launch_bounds__(128, 6)
seal_kernel(
    const int* __restrict__ labels,
    const int* __restrict__ src,
    const int* __restrict__ dst,
    const float* __restrict__ emb,
    const float* __restrict__ w1_0, const float* __restrict__ b1_0,
    const float* __restrict__ w2_0, const float* __restrict__ b2_0,
    const float* __restrict__ w1_1, const float* __restrict__ b1_1,
    const float* __restrict__ w2_1, const float* __restrict__ b2_1,
    const float* __restrict__ w1_2, const float* __restrict__ b1_2,
    const float* __restrict__ w2_2, const float* __restrict__ b2_2,
    const float* __restrict__ conv1_w, const float* __restrict__ conv1_b,
    const float* __restrict__ conv2_w, const float* __restrict__ conv2_b,
    const float* __restrict__ sc_w1, const float* __restrict__ sc_b1,
    const float* __restrict__ sc_w2, const float* __restrict__ sc_b2,
    float* __restrict__ out)
{
    __shared__ __align__(16) float pool[7744];
    __shared__ int nor[10];

    u32* At8 = (u32*)pool;
    float* WB = pool + P_WB;

    const int g = blockIdx.x;
    const int t = threadIdx.x;

    // ---- zero packed adjacency ----
    {
        const uint4 z4 = make_uint4(0u, 0u, 0u, 0u);
        *(uint4*)(At8 + t * 4)            = z4;
        *(uint4*)(At8 + (t + 128) * 4)    = z4;
    }
    __syncthreads();

    // ---- edges + diagonal straight into byte-packed At8; emb load ----
    {
        const int4* s4p = (const int4*)(src + (g << 10));
        const int4* d4p = (const int4*)(dst + (g << 10));
        #pragma unroll
        for (int i = 0; i < 2; i++) {
            const int4 s = s4p[t + i * 128];
            const int4 d = d4p[t + i * 128];
            const int sx = s.x & 63, sy = s.y & 63, sz = s.z & 63, sw = s.w & 63;
            atomicAdd(&At8[(sx >> 2) * 64 + (d.x & 63)], 1u << (8 * (sx & 3)));
            atomicAdd(&At8[(sy >> 2) * 64 + (d.y & 63)], 1u << (8 * (sy & 3)));
            atomicAdd(&At8[(sz >> 2) * 64 + (d.z & 63)], 1u << (8 * (sz & 3)));
            atomicAdd(&At8[(sw >> 2) * 64 + (d.w & 63)], 1u << (8 * (sw & 3)));
        }
        if (t < 64) atomicAdd(&At8[(t >> 2) * 64 + t], 1u << (8 * (t & 3)));  // I + A
    }
    {
        const int n = t >> 1, c0 = (t & 1) * 8;
        const float4 v0 = *(const float4*)(emb + labels[(g << 6) + n] * 16 + c0);
        const float4 v1 = *(const float4*)(emb + labels[(g << 6) + n] * 16 + c0 + 4);
        *(float4*)(pool + P_H0 + n * HS + c0)     = v0;
        *(float4*)(pool + P_H0 + n * HS + c0 + 4) = v1;
    }
    __syncthreads();

    const float* W1s[3] = { w1_0, w1_1, w1_2 };
    const float* B1s[3] = { b1_0, b1_1, b1_2 };
    const float* W2s[3] = { w2_0, w2_1, w2_2 };
    const float* B2s[3] = { b2_0, b2_1, b2_2 };

    float* cur = pool + P_H0;
    float* oth = pool + P_H1;

    #pragma unroll
    for (int l = 0; l < 3; l++) {
        const int din = l ? 32 : 16;

        for (int idx = t; idx < din * 8; idx += 128)
            *(float4*)(WB + idx * 4) = *(const float4*)(W1s[l] + idx * 4);
        for (int idx = t; idx < 256; idx += 128)
            *(float4*)(WB + 1056 + idx * 4) = *(const float4*)(W2s[l] + idx * 4);
        if (t < 32) { WB[1024 + t] = B1s[l][t]; WB[2080 + t] = B2s[l][t]; }
        __syncthreads();

        if (din == 16) agg_frag<16>(At8, cur, oth, t);
        else           agg_frag<32>(At8, cur, oth, t);
        __syncthreads();

        if (din == 16) gemm_frag<16>(oth, cur, WB, WB + 1024, t);
        else           gemm_frag<32>(oth, cur, WB, WB + 1024, t);
        __syncthreads();

        gemm_frag<32>(cur, oth, WB + 1056, WB + 2080, t);
        __syncthreads();

        float* tmp = cur; cur = oth; oth = tmp;
    }
    // cur == pool + P_H1

    // ---- SortPooling: stable rank by channel 31 desc, keep 10 ----
    if (t < 64) {
        const float key = cur[t * HS + 31];
        int r = 0;
        for (int m = 0; m < 64; m++) {
            const float km = cur[m * HS + 31];
            r += (km > key) || (km == key && m < t);
        }
        if (r < 10) nor[r] = t;
    }
    __syncthreads();

    // ---- pooledT extraction (must finish before conv1 staging overwrites) ----
    for (int idx = t; idx < 384; idx += 128) {
        const int ci = idx / 12, r = idx - ci * 12;
        pool[P_PT + ci * 12 + r] = (r < 10) ? cur[nor[r] * HS + ci] : 0.f;
    }
    __syncthreads();

    // ---- conv1 weight staging (overwrites At8/H0/H1 — all dead) ----
    for (int idx = t; idx < 5120; idx += 128) {
        const int co = idx / 160, r = idx - co * 160;
        pool[co * 165 + r] = conv1_w[idx];
    }
    if (t < 32) pool[P_C1B + t] = conv1_b[t];
    __syncthreads();

    // ---- Conv1: 4 warps x 8 input channels; lane = co ----
    {
        const int warp = t >> 5, lane = t & 31;
        float acc[10];
        #pragma unroll
        for (int p = 0; p < 10; p++) acc[p] = 0.f;
        for (int ci = warp * 8; ci < warp * 8 + 8; ci++) {
            float w[5];
            #pragma unroll
            for (int k = 0; k < 5; k++) w[k] = pool[lane * 165 + ci * 5 + k];
            const float4 va = *(const float4*)&pool[P_PT + ci * 12];
            const float4 vb = *(const float4*)&pool[P_PT + ci * 12 + 4];
            const float4 vc = *(const float4*)&pool[P_PT + ci * 12 + 8];
            const float v[12] = { va.x, va.y, va.z, va.w, vb.x, vb.y, vb.z, vb.w,
                                  vc.x, vc.y, vc.z, vc.w };
            #pragma unroll
            for (int p = 0; p < 10; p++) {
                #pragma unroll
                for (int k = 0; k < 5; k++) {
                    const int idx = p + k - 2;
                    if (idx >= 0) acc[p] = fmaf(w[k], v[idx], acc[p]);
                }
            }
        }
        #pragma unroll
        for (int p = 0; p < 10; p++)
            pool[P_PART + warp * 320 + (t & 31) * 10 + p] = acc[p];
    }
    __syncthreads();

    // ---- combine partials + bias + relu + maxpool -> ybufT; conv2 staging ----
    if (t < 32) {
        const int co = t;
        float y[5];
        #pragma unroll
        for (int q = 0; q < 5; q++) {
            float v0 = pool[P_C1B + co], v1 = v0;
            #pragma unroll
            for (int w = 0; w < 4; w++) {
                v0 += pool[P_PART + w * 320 + co * 10 + 2 * q];
                v1 += pool[P_PART + w * 320 + co * 10 + 2 * q + 1];
            }
            y[q] = fmaxf(fmaxf(v0, 0.f), fmaxf(v1, 0.f));
        }
        #pragma unroll
        for (int q = 0; q < 5; q++) pool[P_YB + co * 8 + q] = y[q];
        pool[P_YB + co * 8 + 5] = 0.f;
        pool[P_YB + co * 8 + 6] = 0.f;
        pool[P_YB + co * 8 + 7] = 0.f;
    }
    for (int idx = t; idx < 2560; idx += 128) {
        const int co = idx / 160, r = idx - co * 160;
        pool[co * 165 + r] = conv2_w[idx];        // disjoint from partials/ybuf
    }
    if (t >= 112 && t < 128) pool[P_C2B + (t - 112)] = conv2_b[t - 112];
    __syncthreads();

    // ---- Conv2: lane<16 = co; p = 0..4 ----
    if (t < 16) {
        float acc[5];
        #pragma unroll
        for (int p = 0; p < 5; p++) acc[p] = pool[P_C2B + t];
        for (int ci = 0; ci < 32; ci++) {
            float w[5];
            #pragma unroll
            for (int k = 0; k < 5; k++) w[k] = pool[t * 165 + ci * 5 + k];
            const float4 ya = *(const float4*)&pool[P_YB + ci * 8];
            const float y4 = pool[P_YB + ci * 8 + 4];
            const float a[9] = { 0.f, 0.f, ya.x, ya.y, ya.z, ya.w, y4, 0.f, 0.f };
            #pragma unroll
            for (int p = 0; p < 5; p++)
                #pragma unroll
                for (int k = 0; k < 5; k++)
                    acc[p] = fmaf(w[k], a[p + k], acc[p]);
        }
        #pragma unroll
        for (int p = 0; p < 5; p++)
            pool[P_C2 + t * 5 + p] = fmaxf(acc[p], 0.f);
    }
    __syncthreads();

    if (t < 16) {
        pool[P_FE + t] = 0.2f * (pool[P_C2 + t * 5 + 0] + pool[P_C2 + t * 5 + 1] +
                                 pool[P_C2 + t * 5 + 2] + pool[P_C2 + t * 5 + 3] +
                                 pool[P_C2 + t * 5 + 4]);
    }
    __syncthreads();
    if (t < 16) {
        float a = sc_b1[t];
        #pragma unroll
        for (int i = 0; i < 16; i++) a = fmaf(pool[P_FE + i], sc_w1[i * 16 + t], a);
        pool[P_HI + t] = fmaxf(a, 0.f);
    }
    __syncthreads();
    if (t == 0) {
        float s = sc_b2[0];
        #pragma unroll
        for (int j = 0; j < 16; j++) s = fmaf(pool[P_HI + j], sc_w2[j], s);
        out[g] = s;
    }
}

extern "C" void kernel_launch(void* const* d_in, const int* in_sizes, int n_in,
                              void* d_out, int out_size)
{
    const int B = in_sizes[0] / 64;
    seal_kernel<<<B, 128>>>(
        (const int*)d_in[0], (const int*)d_in[1], (const int*)d_in[2],
        (const float*)d_in[3],
        (const float*)d_in[4],  (const float*)d_in[5],
        (const float*)d_in[6],  (const float*)d_in[7],
        (const float*)d_in[8],  (const float*)d_in[9],
        (const float*)d_in[10], (const float*)d_in[11],
        (const float*)d_in[12], (const float*)d_in[13],
        (const float*)d_in[14], (const float*)d_in[15],
        (const float*)d_in[16], (const float*)d_in[17],
        (const float*)d_in[18], (const float*)d_in[19],
        (const float*)d_in[20], (const float*)d_in[21],
        (const float*)d_in[22], (const float*)d_in[23],
        (float*)d_out);
}